// round 2
// baseline (speedup 1.0000x reference)
#include <cuda_runtime.h>
#include <math.h>

#define NT 256
#define ROWS 8

// shared memory layout (in floats)
#define OFF_H 0        // h state:   8 rows x 8 nodes x 128 = 8192 floats
#define OFF_A 8192     // hn (LN1 out)
#define OFF_B 16384    // k / attO / x-stage / mid(lo half)
#define OFF_C 24576    // v / mid(hi half)
#define OFF_D 32768    // q / att / ln2 chunk / agg
#define SMEM_FLOATS 40960

enum { EPI_STORE=0, EPI_RELU=1, EPI_GELU=2, EPI_ADD=3, EPI_RELU_ADD=4 };

__device__ __forceinline__ float gelu_f(float v) {
    return 0.5f * v * (1.0f + erff(v * 0.70710678118654752440f));
}

// Generic register-tiled GEMM: out[m][j] = act( sum_k A[m][k]*W[k][j] (+ sum A2*W) + bias[j] )
// Thread map: TJ threads along j (4 cols each, float4), TM groups along m (MT rows each).
// Output offset for row m: (m % MI)*s_in + (m / MI)*s_out.
template<int M, int K, int J, int K2, int MI, int EPI>
__device__ __forceinline__ void gemm(
    const float* __restrict__ A,  int lda,
    const float* __restrict__ A2, int lda2,
    const float* __restrict__ W,  int wld,
    const float* __restrict__ bias,
    float* __restrict__ out, int s_in, int s_out)
{
    constexpr int TJ = (J/4 < NT) ? (J/4) : NT;
    constexpr int TM = NT / TJ;
    constexpr int MT = M / TM;
    static_assert(TJ * TM == NT, "thread mapping");
    static_assert(MT * TM == M, "row mapping");

    const int t  = threadIdx.x;
    const int j0 = (t % TJ) * 4;
    const int m0 = (t / TJ) * MT;

    float acc[MT][4];
    #pragma unroll
    for (int i = 0; i < MT; i++) { acc[i][0]=0.f; acc[i][1]=0.f; acc[i][2]=0.f; acc[i][3]=0.f; }

    #pragma unroll 1
    for (int k = 0; k < K; k += 4) {
        const float* Wr = W + (size_t)k * wld + j0;
        float4 w0 = *(const float4*)(Wr + 0 * (size_t)wld);
        float4 w1 = *(const float4*)(Wr + 1 * (size_t)wld);
        float4 w2 = *(const float4*)(Wr + 2 * (size_t)wld);
        float4 w3 = *(const float4*)(Wr + 3 * (size_t)wld);
        #pragma unroll
        for (int mm = 0; mm < MT; mm++) {
            float4 a = *(const float4*)(A + (m0 + mm) * lda + k);
            acc[mm][0] += a.x*w0.x; acc[mm][1] += a.x*w0.y; acc[mm][2] += a.x*w0.z; acc[mm][3] += a.x*w0.w;
            acc[mm][0] += a.y*w1.x; acc[mm][1] += a.y*w1.y; acc[mm][2] += a.y*w1.z; acc[mm][3] += a.y*w1.w;
            acc[mm][0] += a.z*w2.x; acc[mm][1] += a.z*w2.y; acc[mm][2] += a.z*w2.z; acc[mm][3] += a.z*w2.w;
            acc[mm][0] += a.w*w3.x; acc[mm][1] += a.w*w3.y; acc[mm][2] += a.w*w3.z; acc[mm][3] += a.w*w3.w;
        }
    }
    if constexpr (K2 > 0) {
        #pragma unroll 1
        for (int k = 0; k < K2; k += 4) {
            const float* Wr = W + (size_t)(K + k) * wld + j0;
            float4 w0 = *(const float4*)(Wr + 0 * (size_t)wld);
            float4 w1 = *(const float4*)(Wr + 1 * (size_t)wld);
            float4 w2 = *(const float4*)(Wr + 2 * (size_t)wld);
            float4 w3 = *(const float4*)(Wr + 3 * (size_t)wld);
            #pragma unroll
            for (int mm = 0; mm < MT; mm++) {
                float4 a = *(const float4*)(A2 + (m0 + mm) * lda2 + k);
                acc[mm][0] += a.x*w0.x; acc[mm][1] += a.x*w0.y; acc[mm][2] += a.x*w0.z; acc[mm][3] += a.x*w0.w;
                acc[mm][0] += a.y*w1.x; acc[mm][1] += a.y*w1.y; acc[mm][2] += a.y*w1.z; acc[mm][3] += a.y*w1.w;
                acc[mm][0] += a.z*w2.x; acc[mm][1] += a.z*w2.y; acc[mm][2] += a.z*w2.z; acc[mm][3] += a.z*w2.w;
                acc[mm][0] += a.w*w3.x; acc[mm][1] += a.w*w3.y; acc[mm][2] += a.w*w3.z; acc[mm][3] += a.w*w3.w;
            }
        }
    }

    float4 bvec = *(const float4*)(bias + j0);
    float bs[4] = {bvec.x, bvec.y, bvec.z, bvec.w};
    #pragma unroll
    for (int mm = 0; mm < MT; mm++) {
        int m = m0 + mm;
        float* op = out + (m % MI) * s_in + (m / MI) * s_out + j0;
        #pragma unroll
        for (int c = 0; c < 4; c++) {
            float v = acc[mm][c] + bs[c];
            if constexpr (EPI == EPI_STORE)    { op[c] = v; }
            if constexpr (EPI == EPI_RELU)     { op[c] = fmaxf(v, 0.f); }
            if constexpr (EPI == EPI_GELU)     { op[c] = gelu_f(v); }
            if constexpr (EPI == EPI_ADD)      { op[c] += v; }
            if constexpr (EPI == EPI_RELU_ADD) { op[c] += fmaxf(v, 0.f); }
        }
    }
}

// One LayerNorm over 128 elements: whole warp cooperates (lane owns 4 strided elems)
__device__ __forceinline__ void ln_one(const float* __restrict__ src, float* __restrict__ dst,
                                       const float* __restrict__ g, const float* __restrict__ b)
{
    const int lane = threadIdx.x & 31;
    float v0 = src[lane], v1 = src[lane+32], v2 = src[lane+64], v3 = src[lane+96];
    float s  = v0+v1+v2+v3;
    float sq = v0*v0+v1*v1+v2*v2+v3*v3;
    #pragma unroll
    for (int o = 16; o > 0; o >>= 1) {
        s  += __shfl_xor_sync(0xffffffffu, s,  o);
        sq += __shfl_xor_sync(0xffffffffu, sq, o);
    }
    float mean = s * (1.f/128.f);
    float rstd = rsqrtf(sq * (1.f/128.f) - mean*mean + 1e-5f);
    dst[lane]    = (v0-mean)*rstd*g[lane]    + b[lane];
    dst[lane+32] = (v1-mean)*rstd*g[lane+32] + b[lane+32];
    dst[lane+64] = (v2-mean)*rstd*g[lane+64] + b[lane+64];
    dst[lane+96] = (v3-mean)*rstd*g[lane+96] + b[lane+96];
}

__global__ void __launch_bounds__(NT, 1) fused_reasoner(
    const float* __restrict__ x,
    const float* __restrict__ Wp,  const float* __restrict__ bp,
    const float* __restrict__ ln1_g, const float* __restrict__ ln1_b,
    const float* __restrict__ Wq,  const float* __restrict__ bq,
    const float* __restrict__ Wk,  const float* __restrict__ bk,
    const float* __restrict__ Wv,  const float* __restrict__ bv,
    const float* __restrict__ Wo,  const float* __restrict__ bo,
    const float* __restrict__ Wu,  const float* __restrict__ bu,
    const float* __restrict__ ln2_g, const float* __restrict__ ln2_b,
    const float* __restrict__ Wf1, const float* __restrict__ bf1,
    const float* __restrict__ Wf2, const float* __restrict__ bf2,
    const float* __restrict__ Wa,  const float* __restrict__ ba,
    const float* __restrict__ Wout, const float* __restrict__ bout,
    float* __restrict__ out)
{
    extern __shared__ float S[];
    const int t = threadIdx.x;
    const int wid = t >> 5;
    const int row0 = blockIdx.x * ROWS;

    // ---- stage x tile (8 rows x 256) into OFF_B, then h = x @ Wp + bp ----
    {
        const float4* xg = (const float4*)(x + (size_t)row0 * 256);
        float4* xs = (float4*)(S + OFF_B);
        for (int i = t; i < 512; i += NT) xs[i] = xg[i];
    }
    __syncthreads();
    gemm<8,256,1024,0,8,EPI_STORE>(S+OFF_B,256, nullptr,0, Wp,1024, bp, S+OFF_H, 1024, 0);
    __syncthreads();

    #pragma unroll 1
    for (int l = 0; l < 3; l++) {
        const float* wq  = Wq  + l*16384;  const float* wk  = Wk  + l*16384;
        const float* wv  = Wv  + l*16384;  const float* wo  = Wo  + l*16384;
        const float* wu  = Wu  + l*32768;
        const float* wf1 = Wf1 + l*65536;  const float* wf2 = Wf2 + l*65536;
        const float* g1 = ln1_g + l*128;   const float* b1 = ln1_b + l*128;
        const float* g2 = ln2_g + l*128;   const float* b2 = ln2_b + l*128;

        // ---- LN1: hn = LN(h) over all 64 (row,node) pairs ----
        for (int it = 0; it < 8; it++) {
            int p = it * 8 + wid;
            ln_one(S + OFF_H + p*128, S + OFF_A + p*128, g1, b1);
        }
        __syncthreads();

        // ---- Q,K,V projections (M = 64 rows = 8 batch x 8 nodes) ----
        gemm<64,128,128,0,64,EPI_STORE>(S+OFF_A,128, nullptr,0, wq,128, bq+l*128, S+OFF_D, 128, 0);
        gemm<64,128,128,0,64,EPI_STORE>(S+OFF_A,128, nullptr,0, wk,128, bk+l*128, S+OFF_B, 128, 0);
        gemm<64,128,128,0,64,EPI_STORE>(S+OFF_A,128, nullptr,0, wv,128, bv+l*128, S+OFF_C, 128, 0);
        __syncthreads();

        // ---- causal attention: thread = (row, head, query-node); att overwrites own q slice ----
        {
            const int r = t >> 5, head = (t >> 3) & 3, n = t & 7;
            const float* qp = S + OFF_D + (r*8 + n)*128 + head*32;
            float p[8];
            float mx = -1e30f;
            #pragma unroll
            for (int m = 0; m < 8; m++) {
                if (m <= n) {
                    const float* kp = S + OFF_B + (r*8 + m)*128 + head*32;
                    float s = 0.f;
                    #pragma unroll
                    for (int d = 0; d < 32; d++) s += qp[d] * kp[d];
                    s *= 0.17677669529663688f;  // 1/sqrt(32)
                    p[m] = s;
                    mx = fmaxf(mx, s);
                }
            }
            float sum = 0.f;
            #pragma unroll
            for (int m = 0; m < 8; m++) if (m <= n) { p[m] = __expf(p[m] - mx); sum += p[m]; }
            const float inv = 1.f / sum;
            float* ao = S + OFF_D + (r*8 + n)*128 + head*32;
            #pragma unroll
            for (int d = 0; d < 32; d++) {
                float o = 0.f;
                #pragma unroll
                for (int m = 0; m < 8; m++)
                    if (m <= n) o += p[m] * (S + OFF_C)[(r*8 + m)*128 + head*32 + d];
                ao[d] = o * inv;
            }
        }
        __syncthreads();

        // ---- attO = att @ Wo + bo  (into OFF_B; k is dead) ----
        gemm<64,128,128,0,64,EPI_STORE>(S+OFF_D,128, nullptr,0, wo,128, bo+l*128, S+OFF_B, 128, 0);
        __syncthreads();

        // ---- h += relu( [hn | attO] @ Wu + bu ) ----
        gemm<64,128,128,128,64,EPI_RELU_ADD>(S+OFF_A,128, S+OFF_B,128, wu,128, bu+l*128, S+OFF_H, 128, 0);
        __syncthreads();

        // ---- FFN in 2 chunks of 4 nodes (mid = 32 x 512 spans OFF_B..OFF_C) ----
        #pragma unroll 1
        for (int c = 0; c < 2; c++) {
            for (int it = 0; it < 4; it++) {
                int p = it * 8 + wid;             // 0..31 = (r*4 + nn)
                int r = p >> 2, nn = p & 3;
                ln_one(S + OFF_H + (r*8 + c*4 + nn)*128, S + OFF_D + p*128, g2, b2);
            }
            __syncthreads();
            // mid = gelu(hn2 @ Wf1 + bf1), J=512 split into two 256-col halves
            gemm<32,128,256,0,32,EPI_GELU>(S+OFF_D,128, nullptr,0, wf1,     512, bf1+l*512,     S+OFF_B,     512, 0);
            gemm<32,128,256,0,32,EPI_GELU>(S+OFF_D,128, nullptr,0, wf1+256, 512, bf1+l*512+256, S+OFF_B+256, 512, 0);
            __syncthreads();
            // h[:, c*4+nn, :] += mid @ Wf2 + bf2   (m -> (m%4)*128 + (m/4)*1024)
            gemm<32,512,128,0,4,EPI_ADD>(S+OFF_B,512, nullptr,0, wf2,128, bf2+l*128, S+OFF_H + c*4*128, 128, 1024);
            __syncthreads();
        }
    }

    // ---- readout: agg = gelu(flat @ Wa + ba);  out = agg @ Wout + bout ----
    gemm<8,1024,128,0,8,EPI_GELU>(S+OFF_H,1024, nullptr,0, Wa,128, ba, S+OFF_D, 128, 0);
    __syncthreads();
    gemm<8,128,128,0,8,EPI_STORE>(S+OFF_D,128, nullptr,0, Wout,128, bout, out + (size_t)row0*128, 128, 0);
}

extern "C" void kernel_launch(void* const* d_in, const int* in_sizes, int n_in,
                              void* d_out, int out_size)
{
    (void)n_in; (void)out_size;
    const float* x     = (const float*)d_in[0];
    const float* Wp    = (const float*)d_in[1];
    const float* bp    = (const float*)d_in[2];
    const float* ln1_g = (const float*)d_in[3];
    const float* ln1_b = (const float*)d_in[4];
    const float* Wq    = (const float*)d_in[5];
    const float* bq    = (const float*)d_in[6];
    const float* Wk    = (const float*)d_in[7];
    const float* bk    = (const float*)d_in[8];
    const float* Wv    = (const float*)d_in[9];
    const float* bv    = (const float*)d_in[10];
    const float* Wo    = (const float*)d_in[11];
    const float* bo    = (const float*)d_in[12];
    const float* Wu    = (const float*)d_in[13];
    const float* bu    = (const float*)d_in[14];
    const float* ln2_g = (const float*)d_in[15];
    const float* ln2_b = (const float*)d_in[16];
    const float* Wf1   = (const float*)d_in[17];
    const float* bf1   = (const float*)d_in[18];
    const float* Wf2   = (const float*)d_in[19];
    const float* bf2   = (const float*)d_in[20];
    const float* Wa    = (const float*)d_in[21];
    const float* ba    = (const float*)d_in[22];
    const float* Wout  = (const float*)d_in[23];
    const float* bout  = (const float*)d_in[24];

    const int Bsz = in_sizes[0] / 256;       // DIN = 256
    const int grid = Bsz / ROWS;             // B divisible by 8
    const size_t smem = SMEM_FLOATS * sizeof(float);

    cudaFuncSetAttribute(fused_reasoner, cudaFuncAttributeMaxDynamicSharedMemorySize, (int)smem);
    fused_reasoner<<<grid, NT, smem>>>(
        x, Wp, bp, ln1_g, ln1_b, Wq, bq, Wk, bk, Wv, bv, Wo, bo,
        Wu, bu, ln2_g, ln2_b, Wf1, bf1, Wf2, bf2, Wa, ba, Wout, bout,
        (float*)d_out);
}

// round 3
// speedup vs baseline: 1.2989x; 1.2989x over previous
#include <cuda_runtime.h>
#include <math.h>

#define NT 512
#define ROWS 8

// shared memory layout (in floats)
#define OFF_H 0        // h state:   8 rows x 8 nodes x 128 = 8192 floats
#define OFF_A 8192     // hn (LN1 out)
#define OFF_B 16384    // k / attO / x-stage / mid(lo half)
#define OFF_C 24576    // v / mid(hi half)
#define OFF_D 32768    // q / att / ln2 chunk / agg
#define SMEM_FLOATS 40960

enum { EPI_STORE=0, EPI_RELU=1, EPI_GELU=2, EPI_ADD=3, EPI_RELU_ADD=4 };

__device__ __forceinline__ float gelu_f(float v) {
    return 0.5f * v * (1.0f + erff(v * 0.70710678118654752440f));
}

// Generic register-tiled GEMM: out[m][j] = act( sum_k A[m][k]*W[k][j] (+ sum A2*W) + bias[j] )
// Thread map: TJ threads along j (4 cols each, float4), TM groups along m (MT rows each).
// TM is clamped to M; threads >= TJ*TM idle (no internal syncs, safe).
// Output offset for row m: (m % MI)*s_in + (m / MI)*s_out.
template<int M, int K, int J, int K2, int MI, int EPI>
__device__ __forceinline__ void gemm(
    const float* __restrict__ A,  int lda,
    const float* __restrict__ A2, int lda2,
    const float* __restrict__ W,  int wld,
    const float* __restrict__ bias,
    float* __restrict__ out, int s_in, int s_out)
{
    constexpr int TJ    = (J/4 < NT) ? (J/4) : NT;
    constexpr int TMraw = NT / TJ;
    constexpr int TM    = (TMraw < M) ? TMraw : M;
    constexpr int MT    = M / TM;
    static_assert(MT * TM == M, "row mapping");

    const int t = threadIdx.x;
    if (t >= TJ * TM) return;
    const int j0 = (t % TJ) * 4;
    const int m0 = (t / TJ) * MT;

    float acc[MT][4];
    #pragma unroll
    for (int i = 0; i < MT; i++) { acc[i][0]=0.f; acc[i][1]=0.f; acc[i][2]=0.f; acc[i][3]=0.f; }

    #pragma unroll 2
    for (int k = 0; k < K; k += 4) {
        const float* Wr = W + (size_t)k * wld + j0;
        float4 w0 = *(const float4*)(Wr + 0 * (size_t)wld);
        float4 w1 = *(const float4*)(Wr + 1 * (size_t)wld);
        float4 w2 = *(const float4*)(Wr + 2 * (size_t)wld);
        float4 w3 = *(const float4*)(Wr + 3 * (size_t)wld);
        #pragma unroll
        for (int mm = 0; mm < MT; mm++) {
            float4 a = *(const float4*)(A + (m0 + mm) * lda + k);
            acc[mm][0] += a.x*w0.x; acc[mm][1] += a.x*w0.y; acc[mm][2] += a.x*w0.z; acc[mm][3] += a.x*w0.w;
            acc[mm][0] += a.y*w1.x; acc[mm][1] += a.y*w1.y; acc[mm][2] += a.y*w1.z; acc[mm][3] += a.y*w1.w;
            acc[mm][0] += a.z*w2.x; acc[mm][1] += a.z*w2.y; acc[mm][2] += a.z*w2.z; acc[mm][3] += a.z*w2.w;
            acc[mm][0] += a.w*w3.x; acc[mm][1] += a.w*w3.y; acc[mm][2] += a.w*w3.z; acc[mm][3] += a.w*w3.w;
        }
    }
    if constexpr (K2 > 0) {
        #pragma unroll 2
        for (int k = 0; k < K2; k += 4) {
            const float* Wr = W + (size_t)(K + k) * wld + j0;
            float4 w0 = *(const float4*)(Wr + 0 * (size_t)wld);
            float4 w1 = *(const float4*)(Wr + 1 * (size_t)wld);
            float4 w2 = *(const float4*)(Wr + 2 * (size_t)wld);
            float4 w3 = *(const float4*)(Wr + 3 * (size_t)wld);
            #pragma unroll
            for (int mm = 0; mm < MT; mm++) {
                float4 a = *(const float4*)(A2 + (m0 + mm) * lda2 + k);
                acc[mm][0] += a.x*w0.x; acc[mm][1] += a.x*w0.y; acc[mm][2] += a.x*w0.z; acc[mm][3] += a.x*w0.w;
                acc[mm][0] += a.y*w1.x; acc[mm][1] += a.y*w1.y; acc[mm][2] += a.y*w1.z; acc[mm][3] += a.y*w1.w;
                acc[mm][0] += a.z*w2.x; acc[mm][1] += a.z*w2.y; acc[mm][2] += a.z*w2.z; acc[mm][3] += a.z*w2.w;
                acc[mm][0] += a.w*w3.x; acc[mm][1] += a.w*w3.y; acc[mm][2] += a.w*w3.z; acc[mm][3] += a.w*w3.w;
            }
        }
    }

    float4 bvec = *(const float4*)(bias + j0);
    float bs[4] = {bvec.x, bvec.y, bvec.z, bvec.w};
    #pragma unroll
    for (int mm = 0; mm < MT; mm++) {
        int m = m0 + mm;
        float* op = out + (m % MI) * s_in + (m / MI) * s_out + j0;
        #pragma unroll
        for (int c = 0; c < 4; c++) {
            float v = acc[mm][c] + bs[c];
            if constexpr (EPI == EPI_STORE)    { op[c] = v; }
            if constexpr (EPI == EPI_RELU)     { op[c] = fmaxf(v, 0.f); }
            if constexpr (EPI == EPI_GELU)     { op[c] = gelu_f(v); }
            if constexpr (EPI == EPI_ADD)      { op[c] += v; }
            if constexpr (EPI == EPI_RELU_ADD) { op[c] += fmaxf(v, 0.f); }
        }
    }
}

// One LayerNorm over 128 elements: whole warp cooperates (lane owns 4 strided elems)
__device__ __forceinline__ void ln_one(const float* __restrict__ src, float* __restrict__ dst,
                                       const float* __restrict__ g, const float* __restrict__ b)
{
    const int lane = threadIdx.x & 31;
    float v0 = src[lane], v1 = src[lane+32], v2 = src[lane+64], v3 = src[lane+96];
    float s  = v0+v1+v2+v3;
    float sq = v0*v0+v1*v1+v2*v2+v3*v3;
    #pragma unroll
    for (int o = 16; o > 0; o >>= 1) {
        s  += __shfl_xor_sync(0xffffffffu, s,  o);
        sq += __shfl_xor_sync(0xffffffffu, sq, o);
    }
    float mean = s * (1.f/128.f);
    float rstd = rsqrtf(sq * (1.f/128.f) - mean*mean + 1e-5f);
    dst[lane]    = (v0-mean)*rstd*g[lane]    + b[lane];
    dst[lane+32] = (v1-mean)*rstd*g[lane+32] + b[lane+32];
    dst[lane+64] = (v2-mean)*rstd*g[lane+64] + b[lane+64];
    dst[lane+96] = (v3-mean)*rstd*g[lane+96] + b[lane+96];
}

__global__ void __launch_bounds__(NT, 1) fused_reasoner(
    const float* __restrict__ x,
    const float* __restrict__ Wp,  const float* __restrict__ bp,
    const float* __restrict__ ln1_g, const float* __restrict__ ln1_b,
    const float* __restrict__ Wq,  const float* __restrict__ bq,
    const float* __restrict__ Wk,  const float* __restrict__ bk,
    const float* __restrict__ Wv,  const float* __restrict__ bv,
    const float* __restrict__ Wo,  const float* __restrict__ bo,
    const float* __restrict__ Wu,  const float* __restrict__ bu,
    const float* __restrict__ ln2_g, const float* __restrict__ ln2_b,
    const float* __restrict__ Wf1, const float* __restrict__ bf1,
    const float* __restrict__ Wf2, const float* __restrict__ bf2,
    const float* __restrict__ Wa,  const float* __restrict__ ba,
    const float* __restrict__ Wout, const float* __restrict__ bout,
    float* __restrict__ out)
{
    extern __shared__ float S[];
    const int t = threadIdx.x;
    const int wid = t >> 5;            // 0..15
    const int row0 = blockIdx.x * ROWS;

    // ---- stage x tile (8 rows x 256) into OFF_B, then h = x @ Wp + bp ----
    {
        const float4* xg = (const float4*)(x + (size_t)row0 * 256);
        float4* xs = (float4*)(S + OFF_B);
        for (int i = t; i < 512; i += NT) xs[i] = xg[i];
    }
    __syncthreads();
    gemm<8,256,1024,0,8,EPI_STORE>(S+OFF_B,256, nullptr,0, Wp,1024, bp, S+OFF_H, 1024, 0);
    __syncthreads();

    #pragma unroll 1
    for (int l = 0; l < 3; l++) {
        const float* wq  = Wq  + l*16384;  const float* wk  = Wk  + l*16384;
        const float* wv  = Wv  + l*16384;  const float* wo  = Wo  + l*16384;
        const float* wu  = Wu  + l*32768;
        const float* wf1 = Wf1 + l*65536;  const float* wf2 = Wf2 + l*65536;
        const float* g1 = ln1_g + l*128;   const float* b1 = ln1_b + l*128;
        const float* g2 = ln2_g + l*128;   const float* b2 = ln2_b + l*128;

        // ---- LN1: hn = LN(h) over all 64 (row,node) pairs (16 warps x 4) ----
        #pragma unroll
        for (int it = 0; it < 4; it++) {
            int p = it * 16 + wid;
            ln_one(S + OFF_H + p*128, S + OFF_A + p*128, g1, b1);
        }
        __syncthreads();

        // ---- Q,K,V projections (M = 64 rows = 8 batch x 8 nodes) ----
        gemm<64,128,128,0,64,EPI_STORE>(S+OFF_A,128, nullptr,0, wq,128, bq+l*128, S+OFF_D, 128, 0);
        gemm<64,128,128,0,64,EPI_STORE>(S+OFF_A,128, nullptr,0, wk,128, bk+l*128, S+OFF_B, 128, 0);
        gemm<64,128,128,0,64,EPI_STORE>(S+OFF_A,128, nullptr,0, wv,128, bv+l*128, S+OFF_C, 128, 0);
        __syncthreads();

        // ---- causal attention: thread = (row, head, query-node); 256 of 512 threads ----
        if (t < 256) {
            const int r = t >> 5, head = (t >> 3) & 3, n = t & 7;
            const float* qp = S + OFF_D + (r*8 + n)*128 + head*32;
            float p[8];
            float mx = -1e30f;
            #pragma unroll
            for (int m = 0; m < 8; m++) {
                if (m <= n) {
                    const float* kp = S + OFF_B + (r*8 + m)*128 + head*32;
                    float s = 0.f;
                    #pragma unroll
                    for (int d = 0; d < 32; d++) s += qp[d] * kp[d];
                    s *= 0.17677669529663688f;  // 1/sqrt(32)
                    p[m] = s;
                    mx = fmaxf(mx, s);
                }
            }
            float sum = 0.f;
            #pragma unroll
            for (int m = 0; m < 8; m++) if (m <= n) { p[m] = __expf(p[m] - mx); sum += p[m]; }
            const float inv = 1.f / sum;
            float* ao = S + OFF_D + (r*8 + n)*128 + head*32;
            #pragma unroll
            for (int d = 0; d < 32; d++) {
                float o = 0.f;
                #pragma unroll
                for (int m = 0; m < 8; m++)
                    if (m <= n) o += p[m] * (S + OFF_C)[(r*8 + m)*128 + head*32 + d];
                ao[d] = o * inv;
            }
        }
        __syncthreads();

        // ---- attO = att @ Wo + bo  (into OFF_B; k is dead) ----
        gemm<64,128,128,0,64,EPI_STORE>(S+OFF_D,128, nullptr,0, wo,128, bo+l*128, S+OFF_B, 128, 0);
        __syncthreads();

        // ---- h += relu( [hn | attO] @ Wu + bu ) ----
        gemm<64,128,128,128,64,EPI_RELU_ADD>(S+OFF_A,128, S+OFF_B,128, wu,128, bu+l*128, S+OFF_H, 128, 0);
        __syncthreads();

        // ---- FFN in 2 chunks of 4 nodes (mid = 32 x 512 spans OFF_B..OFF_C) ----
        #pragma unroll 1
        for (int c = 0; c < 2; c++) {
            #pragma unroll
            for (int it = 0; it < 2; it++) {
                int p = it * 16 + wid;            // 0..31 = (r*4 + nn)
                int r = p >> 2, nn = p & 3;
                ln_one(S + OFF_H + (r*8 + c*4 + nn)*128, S + OFF_D + p*128, g2, b2);
            }
            __syncthreads();
            // mid = gelu(hn2 @ Wf1 + bf1), J=512 split into two 256-col halves
            gemm<32,128,256,0,32,EPI_GELU>(S+OFF_D,128, nullptr,0, wf1,     512, bf1+l*512,     S+OFF_B,     512, 0);
            gemm<32,128,256,0,32,EPI_GELU>(S+OFF_D,128, nullptr,0, wf1+256, 512, bf1+l*512+256, S+OFF_B+256, 512, 0);
            __syncthreads();
            // h[:, c*4+nn, :] += mid @ Wf2 + bf2   (m -> (m%4)*128 + (m/4)*1024)
            gemm<32,512,128,0,4,EPI_ADD>(S+OFF_B,512, nullptr,0, wf2,128, bf2+l*128, S+OFF_H + c*4*128, 128, 1024);
            __syncthreads();
        }
    }

    // ---- readout: agg = gelu(flat @ Wa + ba);  out = agg @ Wout + bout ----
    gemm<8,1024,128,0,8,EPI_GELU>(S+OFF_H,1024, nullptr,0, Wa,128, ba, S+OFF_D, 128, 0);
    __syncthreads();
    gemm<8,128,128,0,8,EPI_STORE>(S+OFF_D,128, nullptr,0, Wout,128, bout, out + (size_t)row0*128, 128, 0);
}

extern "C" void kernel_launch(void* const* d_in, const int* in_sizes, int n_in,
                              void* d_out, int out_size)
{
    (void)n_in; (void)out_size;
    const float* x     = (const float*)d_in[0];
    const float* Wp    = (const float*)d_in[1];
    const float* bp    = (const float*)d_in[2];
    const float* ln1_g = (const float*)d_in[3];
    const float* ln1_b = (const float*)d_in[4];
    const float* Wq    = (const float*)d_in[5];
    const float* bq    = (const float*)d_in[6];
    const float* Wk    = (const float*)d_in[7];
    const float* bk    = (const float*)d_in[8];
    const float* Wv    = (const float*)d_in[9];
    const float* bv    = (const float*)d_in[10];
    const float* Wo    = (const float*)d_in[11];
    const float* bo    = (const float*)d_in[12];
    const float* Wu    = (const float*)d_in[13];
    const float* bu    = (const float*)d_in[14];
    const float* ln2_g = (const float*)d_in[15];
    const float* ln2_b = (const float*)d_in[16];
    const float* Wf1   = (const float*)d_in[17];
    const float* bf1   = (const float*)d_in[18];
    const float* Wf2   = (const float*)d_in[19];
    const float* bf2   = (const float*)d_in[20];
    const float* Wa    = (const float*)d_in[21];
    const float* ba    = (const float*)d_in[22];
    const float* Wout  = (const float*)d_in[23];
    const float* bout  = (const float*)d_in[24];

    const int Bsz = in_sizes[0] / 256;       // DIN = 256
    const int grid = Bsz / ROWS;             // B divisible by 8
    const size_t smem = SMEM_FLOATS * sizeof(float);

    cudaFuncSetAttribute(fused_reasoner, cudaFuncAttributeMaxDynamicSharedMemorySize, (int)smem);
    fused_reasoner<<<grid, NT, smem>>>(
        x, Wp, bp, ln1_g, ln1_b, Wq, bq, Wk, bk, Wv, bv, Wo, bo,
        Wu, bu, ln2_g, ln2_b, Wf1, bf1, Wf2, bf2, Wa, ba, Wout, bout,
        (float*)d_out);
}